// round 1
// baseline (speedup 1.0000x reference)
#include <cuda_runtime.h>

// Problem dims (fixed by the dataset)
#define NN   8192
#define DIN  4096
#define DOUT 4096
#define RK   256

// Folded effective weight: W_eff = W + diag(b) * B * diag(d) * A   [DOUT, DIN]
__device__ float g_Weff[(size_t)DOUT * DIN];

// Tiling params (classic 128x128x8 SGEMM, 8x8 per thread, 256 threads)
#define BM 128
#define BN 128
#define BK 8
#define TM 8
#define TN 8

// ---------------------------------------------------------------------------
// Kernel 1: fold the VeRA adapter into the weight.
//   W_eff[o][i] = W[o][i] + b[o] * sum_r B[o][r] * d[r] * A[r][i]
// GEMM: M=DOUT (rows o), N=DIN (cols i), K=RK.
//   B_frozen [DOUT][RK]  (K contiguous -> transpose into smem)
//   A_frozen [RK][DIN]   (already [K][N] -> direct smem store, scaled by d[k])
// ---------------------------------------------------------------------------
__global__ __launch_bounds__(256, 2)
void fold_kernel(const float* __restrict__ W,
                 const float* __restrict__ A,
                 const float* __restrict__ Bm,
                 const float* __restrict__ bvec,
                 const float* __restrict__ dvec) {
    __shared__ float Bs[BK][BM];
    __shared__ float As[BK][BN];

    const int tid = threadIdx.x;
    const int m0 = blockIdx.y * BM;   // OUT rows
    const int n0 = blockIdx.x * BN;   // IN cols

    const int loadRowB = tid >> 1;        // 0..127 (o within tile)
    const int loadColB = (tid & 1) * 4;   // 0 or 4 (k within tile)
    const int loadRowA = tid >> 5;        // 0..7   (k within tile)
    const int loadColA = (tid & 31) * 4;  // 0..124 (i within tile)

    const int ty = (tid >> 4) * TM;
    const int tx = (tid & 15) * TN;

    float acc[TM][TN] = {};
    float regM[TM], regN[TN];

    for (int k0 = 0; k0 < RK; k0 += BK) {
        float4 bv = *reinterpret_cast<const float4*>(
            &Bm[(size_t)(m0 + loadRowB) * RK + k0 + loadColB]);
        Bs[loadColB + 0][loadRowB] = bv.x;
        Bs[loadColB + 1][loadRowB] = bv.y;
        Bs[loadColB + 2][loadRowB] = bv.z;
        Bs[loadColB + 3][loadRowB] = bv.w;

        const float dscale = dvec[k0 + loadRowA];
        float4 av = *reinterpret_cast<const float4*>(
            &A[(size_t)(k0 + loadRowA) * DIN + n0 + loadColA]);
        av.x *= dscale; av.y *= dscale; av.z *= dscale; av.w *= dscale;
        *reinterpret_cast<float4*>(&As[loadRowA][loadColA]) = av;

        __syncthreads();

        #pragma unroll
        for (int k = 0; k < BK; k++) {
            #pragma unroll
            for (int i = 0; i < TM; i++) regM[i] = Bs[k][ty + i];
            #pragma unroll
            for (int j = 0; j < TN; j++) regN[j] = As[k][tx + j];
            #pragma unroll
            for (int i = 0; i < TM; i++)
                #pragma unroll
                for (int j = 0; j < TN; j++)
                    acc[i][j] = fmaf(regM[i], regN[j], acc[i][j]);
        }
        __syncthreads();
    }

    #pragma unroll
    for (int i = 0; i < TM; i++) {
        const int o = m0 + ty + i;
        const float bscale = bvec[o];
        #pragma unroll
        for (int j = 0; j < TN; j += 4) {
            const size_t idx = (size_t)o * DIN + n0 + tx + j;
            float4 wv = *reinterpret_cast<const float4*>(&W[idx]);
            float4 r;
            r.x = wv.x + acc[i][j + 0] * bscale;
            r.y = wv.y + acc[i][j + 1] * bscale;
            r.z = wv.z + acc[i][j + 2] * bscale;
            r.w = wv.w + acc[i][j + 3] * bscale;
            *reinterpret_cast<float4*>(&g_Weff[idx]) = r;
        }
    }
}

// ---------------------------------------------------------------------------
// Kernel 2: main GEMM.  out[n][o] = sum_i X[n][i] * W_eff[o][i] + bias[o]
// NT-GEMM: both operands K(=IN)-contiguous; both staged transposed in smem.
// ---------------------------------------------------------------------------
__global__ __launch_bounds__(256, 2)
void main_gemm_kernel(const float* __restrict__ X,
                      const float* __restrict__ bias,
                      float* __restrict__ out) {
    __shared__ float Xs[BK][BM];
    __shared__ float Ws[BK][BN];

    const int tid = threadIdx.x;
    const int m0 = blockIdx.y * BM;   // X rows
    const int n0 = blockIdx.x * BN;   // OUT cols

    const int loadRow = tid >> 1;       // 0..127
    const int loadCol = (tid & 1) * 4;  // 0 or 4 (k within tile)

    const int ty = (tid >> 4) * TM;
    const int tx = (tid & 15) * TN;

    float acc[TM][TN] = {};
    float regM[TM], regN[TN];

    for (int k0 = 0; k0 < DIN; k0 += BK) {
        float4 xv = *reinterpret_cast<const float4*>(
            &X[(size_t)(m0 + loadRow) * DIN + k0 + loadCol]);
        Xs[loadCol + 0][loadRow] = xv.x;
        Xs[loadCol + 1][loadRow] = xv.y;
        Xs[loadCol + 2][loadRow] = xv.z;
        Xs[loadCol + 3][loadRow] = xv.w;

        float4 wv = *reinterpret_cast<const float4*>(
            &g_Weff[(size_t)(n0 + loadRow) * DIN + k0 + loadCol]);
        Ws[loadCol + 0][loadRow] = wv.x;
        Ws[loadCol + 1][loadRow] = wv.y;
        Ws[loadCol + 2][loadRow] = wv.z;
        Ws[loadCol + 3][loadRow] = wv.w;

        __syncthreads();

        #pragma unroll
        for (int k = 0; k < BK; k++) {
            #pragma unroll
            for (int i = 0; i < TM; i++) regM[i] = Xs[k][ty + i];
            #pragma unroll
            for (int j = 0; j < TN; j++) regN[j] = Ws[k][tx + j];
            #pragma unroll
            for (int i = 0; i < TM; i++)
                #pragma unroll
                for (int j = 0; j < TN; j++)
                    acc[i][j] = fmaf(regM[i], regN[j], acc[i][j]);
        }
        __syncthreads();
    }

    #pragma unroll
    for (int i = 0; i < TM; i++) {
        const int row = m0 + ty + i;
        #pragma unroll
        for (int j = 0; j < TN; j += 4) {
            const int col = n0 + tx + j;
            const float4 bb = *reinterpret_cast<const float4*>(&bias[col]);
            float4 r;
            r.x = acc[i][j + 0] + bb.x;
            r.y = acc[i][j + 1] + bb.y;
            r.z = acc[i][j + 2] + bb.z;
            r.w = acc[i][j + 3] + bb.w;
            *reinterpret_cast<float4*>(&out[(size_t)row * DOUT + col]) = r;
        }
    }
}

// ---------------------------------------------------------------------------
// Harness entry. Inputs (metadata order): x, W, bias, A_frozen, B_frozen,
// b_vec, d_vec. Output: float32 [NN, DOUT].
// ---------------------------------------------------------------------------
extern "C" void kernel_launch(void* const* d_in, const int* in_sizes, int n_in,
                              void* d_out, int out_size) {
    const float* x    = (const float*)d_in[0];
    const float* W    = (const float*)d_in[1];
    const float* bias = (const float*)d_in[2];
    const float* A    = (const float*)d_in[3];
    const float* Bm   = (const float*)d_in[4];
    const float* bvec = (const float*)d_in[5];
    const float* dvec = (const float*)d_in[6];
    float* out = (float*)d_out;

    {
        dim3 grid(DIN / BN, DOUT / BM);   // 32 x 32
        dim3 block(256);
        fold_kernel<<<grid, block>>>(W, A, Bm, bvec, dvec);
    }
    {
        dim3 grid(DOUT / BN, NN / BM);    // 32 x 64
        dim3 block(256);
        main_gemm_kernel<<<grid, block>>>(x, bias, out);
    }
}

// round 3
// speedup vs baseline: 2.9733x; 2.9733x over previous
#include <cuda_runtime.h>
#include <cuda_bf16.h>
#include <cstdint>

// Problem dims (fixed)
#define NN   8192
#define DIN  4096
#define DOUT 4096
#define RK   256

// ---------------------------------------------------------------------------
// Device scratch (no runtime allocation allowed)
// ---------------------------------------------------------------------------
__device__ __align__(256) __nv_bfloat16 g_xh[(size_t)NN * DIN];    // 64 MB
__device__ __align__(256) __nv_bfloat16 g_xl[(size_t)NN * DIN];    // 64 MB
__device__ __align__(256) __nv_bfloat16 g_wh[(size_t)DOUT * DIN];  // 32 MB
__device__ __align__(256) __nv_bfloat16 g_wl[(size_t)DOUT * DIN];  // 32 MB

// ---------------------------------------------------------------------------
// PTX helpers (baseline ISA only: cp.async, ldmatrix, mma.sync)
// ---------------------------------------------------------------------------
__device__ __forceinline__ uint32_t smem_u32(const void* p) {
    uint32_t a;
    asm("{ .reg .u64 t; cvta.to.shared.u64 t, %1; cvt.u32.u64 %0, t; }" : "=r"(a) : "l"(p));
    return a;
}

#define CP_ASYNC16(dst, src) \
    asm volatile("cp.async.cg.shared.global [%0], [%1], 16;" :: "r"(dst), "l"(src) : "memory")
#define CP_ASYNC_COMMIT() asm volatile("cp.async.commit_group;" ::: "memory")
#define CP_ASYNC_WAIT(n)  asm volatile("cp.async.wait_group %0;" :: "n"(n) : "memory")

__device__ __forceinline__ void ldmatrix_x4(uint32_t* r, uint32_t addr) {
    asm volatile("ldmatrix.sync.aligned.m8n8.x4.shared.b16 {%0,%1,%2,%3}, [%4];"
                 : "=r"(r[0]), "=r"(r[1]), "=r"(r[2]), "=r"(r[3]) : "r"(addr));
}

__device__ __forceinline__ void mma16816(float* c, const uint32_t* a, const uint32_t* b) {
    asm volatile(
        "mma.sync.aligned.m16n8k16.row.col.f32.bf16.bf16.f32 "
        "{%0,%1,%2,%3}, {%4,%5,%6,%7}, {%8,%9}, {%0,%1,%2,%3};"
        : "+f"(c[0]), "+f"(c[1]), "+f"(c[2]), "+f"(c[3])
        : "r"(a[0]), "r"(a[1]), "r"(a[2]), "r"(a[3]), "r"(b[0]), "r"(b[1]));
}

__device__ __forceinline__ uint32_t swz(uint32_t off) {   // SW128: bits[6:4] ^= bits[9:7]
    return off ^ ((off >> 3) & 0x70);
}

// ---------------------------------------------------------------------------
// Kernel 1: split x -> bf16 hi/lo
// ---------------------------------------------------------------------------
__global__ __launch_bounds__(256)
void split_x_kernel(const float* __restrict__ x) {
    size_t i = ((size_t)blockIdx.x * blockDim.x + threadIdx.x) * 8;
    float4 a = *reinterpret_cast<const float4*>(x + i);
    float4 b = *reinterpret_cast<const float4*>(x + i + 4);
    float v[8] = {a.x, a.y, a.z, a.w, b.x, b.y, b.z, b.w};
    __align__(16) __nv_bfloat16 h[8];
    __align__(16) __nv_bfloat16 l[8];
    #pragma unroll
    for (int j = 0; j < 8; j++) {
        h[j] = __float2bfloat16_rn(v[j]);
        l[j] = __float2bfloat16_rn(v[j] - __bfloat162float(h[j]));
    }
    *reinterpret_cast<uint4*>(&g_xh[i]) = *reinterpret_cast<uint4*>(h);
    *reinterpret_cast<uint4*>(&g_xl[i]) = *reinterpret_cast<uint4*>(l);
}

// ---------------------------------------------------------------------------
// Kernel 2: fold VeRA into W, output split bf16 hi/lo.
//   W_eff[o][i] = W[o][i] + b[o] * sum_r B[o][r] * d[r] * A[r][i]
// ---------------------------------------------------------------------------
#define BMF 128
#define BNF 128
#define BKF 8
#define TMF 8
#define TNF 8

__global__ __launch_bounds__(256, 2)
void fold_kernel(const float* __restrict__ W,
                 const float* __restrict__ A,
                 const float* __restrict__ Bm,
                 const float* __restrict__ bvec,
                 const float* __restrict__ dvec) {
    __shared__ float Bs[BKF][BMF];
    __shared__ float As[BKF][BNF];

    const int tid = threadIdx.x;
    const int m0 = blockIdx.y * BMF;
    const int n0 = blockIdx.x * BNF;

    const int loadRowB = tid >> 1;
    const int loadColB = (tid & 1) * 4;
    const int loadRowA = tid >> 5;
    const int loadColA = (tid & 31) * 4;

    const int ty = (tid >> 4) * TMF;
    const int tx = (tid & 15) * TNF;

    float acc[TMF][TNF] = {};
    float regM[TMF], regN[TNF];

    for (int k0 = 0; k0 < RK; k0 += BKF) {
        float4 bv = *reinterpret_cast<const float4*>(
            &Bm[(size_t)(m0 + loadRowB) * RK + k0 + loadColB]);
        Bs[loadColB + 0][loadRowB] = bv.x;
        Bs[loadColB + 1][loadRowB] = bv.y;
        Bs[loadColB + 2][loadRowB] = bv.z;
        Bs[loadColB + 3][loadRowB] = bv.w;

        const float dscale = dvec[k0 + loadRowA];
        float4 av = *reinterpret_cast<const float4*>(
            &A[(size_t)(k0 + loadRowA) * DIN + n0 + loadColA]);
        av.x *= dscale; av.y *= dscale; av.z *= dscale; av.w *= dscale;
        *reinterpret_cast<float4*>(&As[loadRowA][loadColA]) = av;

        __syncthreads();

        #pragma unroll
        for (int k = 0; k < BKF; k++) {
            #pragma unroll
            for (int i = 0; i < TMF; i++) regM[i] = Bs[k][ty + i];
            #pragma unroll
            for (int j = 0; j < TNF; j++) regN[j] = As[k][tx + j];
            #pragma unroll
            for (int i = 0; i < TMF; i++)
                #pragma unroll
                for (int j = 0; j < TNF; j++)
                    acc[i][j] = fmaf(regM[i], regN[j], acc[i][j]);
        }
        __syncthreads();
    }

    #pragma unroll
    for (int i = 0; i < TMF; i++) {
        const int o = m0 + ty + i;
        const float bscale = bvec[o];
        __align__(16) __nv_bfloat16 h[TNF];
        __align__(16) __nv_bfloat16 l[TNF];
        #pragma unroll
        for (int j = 0; j < TNF; j += 4) {
            const size_t idx = (size_t)o * DIN + n0 + tx + j;
            float4 wv = *reinterpret_cast<const float4*>(&W[idx]);
            float r[4] = {wv.x + acc[i][j + 0] * bscale,
                          wv.y + acc[i][j + 1] * bscale,
                          wv.z + acc[i][j + 2] * bscale,
                          wv.w + acc[i][j + 3] * bscale};
            #pragma unroll
            for (int q = 0; q < 4; q++) {
                h[j + q] = __float2bfloat16_rn(r[q]);
                l[j + q] = __float2bfloat16_rn(r[q] - __bfloat162float(h[j + q]));
            }
        }
        const size_t base = (size_t)o * DIN + n0 + tx;
        *reinterpret_cast<uint4*>(&g_wh[base]) = *reinterpret_cast<uint4*>(h);
        *reinterpret_cast<uint4*>(&g_wl[base]) = *reinterpret_cast<uint4*>(l);
    }
}

// ---------------------------------------------------------------------------
// Kernel 3: main GEMM via mma.sync bf16, split-K-concat 3-term compensation.
//   out[m][n] = sum_keff  A'[m][keff] * B'[n][keff] + bias[n]
// where K_eff = 3*DIN, phase 0: (xh,wh), 1: (xl,wh), 2: (xh,wl).
// CTA tile 128x256, KC=64 bf16/chunk, 3-stage cp.async pipeline, 512 threads.
// ---------------------------------------------------------------------------
#define BM 128
#define BN 256
#define KC 64
#define NCHUNK (3 * DIN / KC)          // 192
#define A_BYTES (BM * 128)             // 16384
#define B_BYTES (BN * 128)             // 32768
#define STAGE_BYTES (A_BYTES + B_BYTES) // 49152
#define NSTAGE 3
#define SMEM_TOTAL (NSTAGE * STAGE_BYTES)  // 147456

__device__ __forceinline__ void load_chunk(int chunk, uint32_t st, int tid,
                                           int m0, int n0) {
    const int p = chunk >> 6;                 // phase 0..2
    const int koff = (chunk & 63) * KC;       // element offset in [0, DIN)
    const __nv_bfloat16* __restrict__ Asrc = (p == 1) ? g_xl : g_xh;
    const __nv_bfloat16* __restrict__ Bsrc = (p == 2) ? g_wl : g_wh;

    const int seg = tid & 7;        // 16B segment within 128B row
    const int rb  = tid >> 3;       // 0..63
    #pragma unroll
    for (int t = 0; t < 2; t++) {   // A: 128 rows
        const int r = t * 64 + rb;
        const __nv_bfloat16* g = Asrc + (size_t)(m0 + r) * DIN + koff + seg * 8;
        uint32_t off = r * 128 + seg * 16;
        CP_ASYNC16(st + swz(off), g);
    }
    #pragma unroll
    for (int t = 0; t < 4; t++) {   // B: 256 rows
        const int r = t * 64 + rb;
        const __nv_bfloat16* g = Bsrc + (size_t)(n0 + r) * DIN + koff + seg * 8;
        uint32_t off = r * 128 + seg * 16;
        CP_ASYNC16(st + A_BYTES + swz(off), g);
    }
}

__global__ __launch_bounds__(512, 1)
void gemm_mma_kernel(const float* __restrict__ bias, float* __restrict__ out) {
    extern __shared__ char smem[];
    const uint32_t sb = smem_u32(smem);
    const int tid  = threadIdx.x;
    const int lane = tid & 31;
    const int wid  = tid >> 5;          // 0..15
    const int warp_m = wid & 1;         // 0..1  -> 64-row slab
    const int warp_n = wid >> 1;        // 0..7  -> 32-col slab

    const int n0 = blockIdx.x * BN;
    const int m0 = blockIdx.y * BM;

    float acc[4][4][4] = {};            // [mt][nt][4]

    // ldmatrix lane addressing (element units)
    const int arow = lane & 15;                         // A row within 16
    const int acol = (lane >> 4) * 8;                   // A k-seg
    const int brow = (lane & 7) + ((lane >> 4) << 3);   // B row within 16
    const int bcol = ((lane >> 3) & 1) * 8;             // B k-seg

    // Prologue: stages 0,1
    load_chunk(0, sb, tid, m0, n0);
    CP_ASYNC_COMMIT();
    load_chunk(1, sb + STAGE_BYTES, tid, m0, n0);
    CP_ASYNC_COMMIT();

    for (int i = 0; i < NCHUNK; i++) {
        const int stage = i % NSTAGE;
        const uint32_t st = sb + stage * STAGE_BYTES;

        if (i < NCHUNK - 1) { CP_ASYNC_WAIT(1); } else { CP_ASYNC_WAIT(0); }
        __syncthreads();

        if (i + 2 < NCHUNK) {
            load_chunk(i + 2, sb + ((i + 2) % NSTAGE) * STAGE_BYTES, tid, m0, n0);
            CP_ASYNC_COMMIT();
        }

        // Compute this stage: 4 k16 steps
        #pragma unroll
        for (int ks = 0; ks < 4; ks++) {
            uint32_t a[4][4];
            #pragma unroll
            for (int mt = 0; mt < 4; mt++) {
                uint32_t off = (uint32_t)(warp_m * 64 + mt * 16 + arow) * 128
                             + (ks * 16 + acol) * 2;
                ldmatrix_x4(a[mt], st + swz(off));
            }
            uint32_t b[4][2];
            #pragma unroll
            for (int bg = 0; bg < 2; bg++) {
                uint32_t r[4];
                uint32_t off = (uint32_t)(warp_n * 32 + bg * 16 + brow) * 128
                             + (ks * 16 + bcol) * 2;
                ldmatrix_x4(r, st + A_BYTES + swz(off));
                b[bg * 2 + 0][0] = r[0]; b[bg * 2 + 0][1] = r[1];
                b[bg * 2 + 1][0] = r[2]; b[bg * 2 + 1][1] = r[3];
            }
            #pragma unroll
            for (int mt = 0; mt < 4; mt++)
                #pragma unroll
                for (int nt = 0; nt < 4; nt++)
                    mma16816(acc[mt][nt], a[mt], b[nt]);
        }
        __syncthreads();
    }

    // Epilogue: write accumulators + bias
    const int r0 = m0 + warp_m * 64 + (lane >> 2);
    const int c0 = n0 + warp_n * 32 + (lane & 3) * 2;
    #pragma unroll
    for (int mt = 0; mt < 4; mt++) {
        const int rm = r0 + mt * 16;
        #pragma unroll
        for (int nt = 0; nt < 4; nt++) {
            const int cb = c0 + nt * 8;
            const float2 bb = *reinterpret_cast<const float2*>(&bias[cb]);
            float2 v0, v1;
            v0.x = acc[mt][nt][0] + bb.x;
            v0.y = acc[mt][nt][1] + bb.y;
            v1.x = acc[mt][nt][2] + bb.x;
            v1.y = acc[mt][nt][3] + bb.y;
            *reinterpret_cast<float2*>(&out[(size_t)rm * DOUT + cb]) = v0;
            *reinterpret_cast<float2*>(&out[(size_t)(rm + 8) * DOUT + cb]) = v1;
        }
    }
}

// ---------------------------------------------------------------------------
// Harness entry. Inputs: x, W, bias, A_frozen, B_frozen, b_vec, d_vec.
// ---------------------------------------------------------------------------
extern "C" void kernel_launch(void* const* d_in, const int* in_sizes, int n_in,
                              void* d_out, int out_size) {
    const float* x    = (const float*)d_in[0];
    const float* W    = (const float*)d_in[1];
    const float* bias = (const float*)d_in[2];
    const float* A    = (const float*)d_in[3];
    const float* Bm   = (const float*)d_in[4];
    const float* bvec = (const float*)d_in[5];
    const float* dvec = (const float*)d_in[6];
    float* out = (float*)d_out;

    {   // split x into bf16 hi/lo
        size_t total = (size_t)NN * DIN / 8;
        split_x_kernel<<<(unsigned)(total / 256), 256>>>(x);
    }
    {   // fold adapter into W, write bf16 hi/lo
        dim3 grid(DIN / BNF, DOUT / BMF);
        fold_kernel<<<grid, 256>>>(W, A, Bm, bvec, dvec);
    }
    {   // tensor-core main GEMM (mma.sync)
        static int attr_set = 0;
        if (!attr_set) {
            cudaFuncSetAttribute(gemm_mma_kernel,
                                 cudaFuncAttributeMaxDynamicSharedMemorySize, SMEM_TOTAL);
            attr_set = 1;
        }
        dim3 grid(DOUT / BN, NN / BM);   // 16 x 64
        gemm_mma_kernel<<<grid, 512, SMEM_TOTAL>>>(bias, out);
    }
}

// round 5
// speedup vs baseline: 7.3123x; 2.4593x over previous
#include <cuda_runtime.h>
#include <cuda_fp16.h>
#include <cstdint>

// Problem dims (fixed)
#define NN   8192
#define DIN  4096
#define DOUT 4096
#define RK   256

// ---------------------------------------------------------------------------
// Device scratch (no runtime allocation allowed)
// ---------------------------------------------------------------------------
__device__ __align__(256) __half g_x16[(size_t)NN * DIN];    // 64 MB
__device__ __align__(256) __half g_w16[(size_t)DOUT * DIN];  // 32 MB

// ---------------------------------------------------------------------------
// PTX helpers (baseline ISA only: cp.async, ldmatrix, mma.sync)
// ---------------------------------------------------------------------------
__device__ __forceinline__ uint32_t smem_u32(const void* p) {
    uint32_t a;
    asm("{ .reg .u64 t; cvta.to.shared.u64 t, %1; cvt.u32.u64 %0, t; }" : "=r"(a) : "l"(p));
    return a;
}

#define CP_ASYNC16(dst, src) \
    asm volatile("cp.async.cg.shared.global [%0], [%1], 16;" :: "r"(dst), "l"(src) : "memory")
#define CP_ASYNC_COMMIT() asm volatile("cp.async.commit_group;" ::: "memory")
#define CP_ASYNC_WAIT(n)  asm volatile("cp.async.wait_group %0;" :: "n"(n) : "memory")

__device__ __forceinline__ void ldmatrix_x4(uint32_t* r, uint32_t addr) {
    asm volatile("ldmatrix.sync.aligned.m8n8.x4.shared.b16 {%0,%1,%2,%3}, [%4];"
                 : "=r"(r[0]), "=r"(r[1]), "=r"(r[2]), "=r"(r[3]) : "r"(addr));
}

__device__ __forceinline__ void mma16816(float* c, const uint32_t* a, const uint32_t* b) {
    asm volatile(
        "mma.sync.aligned.m16n8k16.row.col.f32.f16.f16.f32 "
        "{%0,%1,%2,%3}, {%4,%5,%6,%7}, {%8,%9}, {%0,%1,%2,%3};"
        : "+f"(c[0]), "+f"(c[1]), "+f"(c[2]), "+f"(c[3])
        : "r"(a[0]), "r"(a[1]), "r"(a[2]), "r"(a[3]), "r"(b[0]), "r"(b[1]));
}

__device__ __forceinline__ uint32_t swz(uint32_t off) {   // SW128: bits[6:4] ^= bits[9:7]
    return off ^ ((off >> 3) & 0x70);
}

// ---------------------------------------------------------------------------
// Kernel 1: convert x -> fp16
// ---------------------------------------------------------------------------
__global__ __launch_bounds__(256)
void conv_x_kernel(const float* __restrict__ x) {
    size_t i = ((size_t)blockIdx.x * blockDim.x + threadIdx.x) * 8;
    float4 a = *reinterpret_cast<const float4*>(x + i);
    float4 b = *reinterpret_cast<const float4*>(x + i + 4);
    float v[8] = {a.x, a.y, a.z, a.w, b.x, b.y, b.z, b.w};
    __align__(16) __half h[8];
    #pragma unroll
    for (int j = 0; j < 8; j++) h[j] = __float2half_rn(v[j]);
    *reinterpret_cast<uint4*>(&g_x16[i]) = *reinterpret_cast<uint4*>(h);
}

// ---------------------------------------------------------------------------
// Kernel 2: fold VeRA into W, output fp16.
//   W_eff[o][i] = W[o][i] + b[o] * sum_r B[o][r] * d[r] * A[r][i]
// ---------------------------------------------------------------------------
#define BMF 128
#define BNF 128
#define BKF 8
#define TMF 8
#define TNF 8

__global__ __launch_bounds__(256, 2)
void fold_kernel(const float* __restrict__ W,
                 const float* __restrict__ A,
                 const float* __restrict__ Bm,
                 const float* __restrict__ bvec,
                 const float* __restrict__ dvec) {
    __shared__ float Bs[BKF][BMF];
    __shared__ float As[BKF][BNF];

    const int tid = threadIdx.x;
    const int m0 = blockIdx.y * BMF;
    const int n0 = blockIdx.x * BNF;

    const int loadRowB = tid >> 1;
    const int loadColB = (tid & 1) * 4;
    const int loadRowA = tid >> 5;
    const int loadColA = (tid & 31) * 4;

    const int ty = (tid >> 4) * TMF;
    const int tx = (tid & 15) * TNF;

    float acc[TMF][TNF] = {};
    float regM[TMF], regN[TNF];

    for (int k0 = 0; k0 < RK; k0 += BKF) {
        float4 bv = *reinterpret_cast<const float4*>(
            &Bm[(size_t)(m0 + loadRowB) * RK + k0 + loadColB]);
        Bs[loadColB + 0][loadRowB] = bv.x;
        Bs[loadColB + 1][loadRowB] = bv.y;
        Bs[loadColB + 2][loadRowB] = bv.z;
        Bs[loadColB + 3][loadRowB] = bv.w;

        const float dscale = dvec[k0 + loadRowA];
        float4 av = *reinterpret_cast<const float4*>(
            &A[(size_t)(k0 + loadRowA) * DIN + n0 + loadColA]);
        av.x *= dscale; av.y *= dscale; av.z *= dscale; av.w *= dscale;
        *reinterpret_cast<float4*>(&As[loadRowA][loadColA]) = av;

        __syncthreads();

        #pragma unroll
        for (int k = 0; k < BKF; k++) {
            #pragma unroll
            for (int i = 0; i < TMF; i++) regM[i] = Bs[k][ty + i];
            #pragma unroll
            for (int j = 0; j < TNF; j++) regN[j] = As[k][tx + j];
            #pragma unroll
            for (int i = 0; i < TMF; i++)
                #pragma unroll
                for (int j = 0; j < TNF; j++)
                    acc[i][j] = fmaf(regM[i], regN[j], acc[i][j]);
        }
        __syncthreads();
    }

    #pragma unroll
    for (int i = 0; i < TMF; i++) {
        const int o = m0 + ty + i;
        const float bscale = bvec[o];
        __align__(16) __half h[TNF];
        #pragma unroll
        for (int j = 0; j < TNF; j += 4) {
            const size_t idx = (size_t)o * DIN + n0 + tx + j;
            float4 wv = *reinterpret_cast<const float4*>(&W[idx]);
            h[j + 0] = __float2half_rn(wv.x + acc[i][j + 0] * bscale);
            h[j + 1] = __float2half_rn(wv.y + acc[i][j + 1] * bscale);
            h[j + 2] = __float2half_rn(wv.z + acc[i][j + 2] * bscale);
            h[j + 3] = __float2half_rn(wv.w + acc[i][j + 3] * bscale);
        }
        *reinterpret_cast<uint4*>(&g_w16[(size_t)o * DIN + n0 + tx]) =
            *reinterpret_cast<uint4*>(h);
    }
}

// ---------------------------------------------------------------------------
// Kernel 3: main GEMM via mma.sync fp16, single pass, K = DIN.
//   out[m][n] = sum_k x16[m][k] * w16[n][k] + bias[n]
// CTA tile 128x256, KC=64 fp16/chunk (128 B/row), 3-stage cp.async, 512 thr.
// ---------------------------------------------------------------------------
#define BM 128
#define BN 256
#define KC 64
#define NCHUNK (DIN / KC)               // 64
#define A_BYTES (BM * 128)              // 16384
#define B_BYTES (BN * 128)              // 32768
#define STAGE_BYTES (A_BYTES + B_BYTES) // 49152
#define NSTAGE 3
#define SMEM_TOTAL (NSTAGE * STAGE_BYTES)  // 147456

__device__ __forceinline__ void load_chunk(int chunk, uint32_t st, int tid,
                                           int m0, int n0) {
    const int koff = chunk * KC;
    const int seg = tid & 7;        // 16B segment within 128B row
    const int rb  = tid >> 3;       // 0..63
    #pragma unroll
    for (int t = 0; t < 2; t++) {   // A: 128 rows
        const int r = t * 64 + rb;
        const __half* g = g_x16 + (size_t)(m0 + r) * DIN + koff + seg * 8;
        uint32_t off = r * 128 + seg * 16;
        CP_ASYNC16(st + swz(off), g);
    }
    #pragma unroll
    for (int t = 0; t < 4; t++) {   // B: 256 rows
        const int r = t * 64 + rb;
        const __half* g = g_w16 + (size_t)(n0 + r) * DIN + koff + seg * 8;
        uint32_t off = r * 128 + seg * 16;
        CP_ASYNC16(st + A_BYTES + swz(off), g);
    }
}

__global__ __launch_bounds__(512, 1)
void gemm_mma_kernel(const float* __restrict__ bias, float* __restrict__ out) {
    extern __shared__ char smem[];
    const uint32_t sb = smem_u32(smem);
    const int tid  = threadIdx.x;
    const int lane = tid & 31;
    const int wid  = tid >> 5;          // 0..15
    const int warp_m = wid & 1;         // 0..1  -> 64-row slab
    const int warp_n = wid >> 1;        // 0..7  -> 32-col slab

    const int n0 = blockIdx.x * BN;
    const int m0 = blockIdx.y * BM;

    float acc[4][4][4] = {};            // [mt][nt][4]

    // ldmatrix lane addressing (element units)
    const int arow = lane & 15;                         // A row within 16
    const int acol = (lane >> 4) * 8;                   // A k-seg
    const int brow = (lane & 7) + ((lane >> 4) << 3);   // B row within 16
    const int bcol = ((lane >> 3) & 1) * 8;             // B k-seg

    // Prologue: stages 0,1
    load_chunk(0, sb, tid, m0, n0);
    CP_ASYNC_COMMIT();
    load_chunk(1, sb + STAGE_BYTES, tid, m0, n0);
    CP_ASYNC_COMMIT();

    for (int i = 0; i < NCHUNK; i++) {
        const int stage = i % NSTAGE;
        const uint32_t st = sb + stage * STAGE_BYTES;

        if (i < NCHUNK - 1) { CP_ASYNC_WAIT(1); } else { CP_ASYNC_WAIT(0); }
        __syncthreads();

        if (i + 2 < NCHUNK) {
            load_chunk(i + 2, sb + ((i + 2) % NSTAGE) * STAGE_BYTES, tid, m0, n0);
            CP_ASYNC_COMMIT();
        }

        // Compute this stage: 4 k16 steps
        #pragma unroll
        for (int ks = 0; ks < 4; ks++) {
            uint32_t a[4][4];
            #pragma unroll
            for (int mt = 0; mt < 4; mt++) {
                uint32_t off = (uint32_t)(warp_m * 64 + mt * 16 + arow) * 128
                             + (ks * 16 + acol) * 2;
                ldmatrix_x4(a[mt], st + swz(off));
            }
            uint32_t b[4][2];
            #pragma unroll
            for (int bg = 0; bg < 2; bg++) {
                uint32_t r[4];
                uint32_t off = (uint32_t)(warp_n * 32 + bg * 16 + brow) * 128
                             + (ks * 16 + bcol) * 2;
                ldmatrix_x4(r, st + A_BYTES + swz(off));
                b[bg * 2 + 0][0] = r[0]; b[bg * 2 + 0][1] = r[1];
                b[bg * 2 + 1][0] = r[2]; b[bg * 2 + 1][1] = r[3];
            }
            #pragma unroll
            for (int mt = 0; mt < 4; mt++)
                #pragma unroll
                for (int nt = 0; nt < 4; nt++)
                    mma16816(acc[mt][nt], a[mt], b[nt]);
        }
        __syncthreads();
    }

    // Epilogue: write accumulators + bias
    const int r0 = m0 + warp_m * 64 + (lane >> 2);
    const int c0 = n0 + warp_n * 32 + (lane & 3) * 2;
    #pragma unroll
    for (int mt = 0; mt < 4; mt++) {
        const int rm = r0 + mt * 16;
        #pragma unroll
        for (int nt = 0; nt < 4; nt++) {
            const int cb = c0 + nt * 8;
            const float2 bb = *reinterpret_cast<const float2*>(&bias[cb]);
            float2 v0, v1;
            v0.x = acc[mt][nt][0] + bb.x;
            v0.y = acc[mt][nt][1] + bb.y;
            v1.x = acc[mt][nt][2] + bb.x;
            v1.y = acc[mt][nt][3] + bb.y;
            *reinterpret_cast<float2*>(&out[(size_t)rm * DOUT + cb]) = v0;
            *reinterpret_cast<float2*>(&out[(size_t)(rm + 8) * DOUT + cb]) = v1;
        }
    }
}

// ---------------------------------------------------------------------------
// Harness entry. Inputs: x, W, bias, A_frozen, B_frozen, b_vec, d_vec.
// ---------------------------------------------------------------------------
extern "C" void kernel_launch(void* const* d_in, const int* in_sizes, int n_in,
                              void* d_out, int out_size) {
    const float* x    = (const float*)d_in[0];
    const float* W    = (const float*)d_in[1];
    const float* bias = (const float*)d_in[2];
    const float* A    = (const float*)d_in[3];
    const float* Bm   = (const float*)d_in[4];
    const float* bvec = (const float*)d_in[5];
    const float* dvec = (const float*)d_in[6];
    float* out = (float*)d_out;

    {   // convert x to fp16
        size_t total = (size_t)NN * DIN / 8;
        conv_x_kernel<<<(unsigned)(total / 256), 256>>>(x);
    }
    {   // fold adapter into W, write fp16
        dim3 grid(DIN / BNF, DOUT / BMF);
        fold_kernel<<<grid, 256>>>(W, A, Bm, bvec, dvec);
    }
    {   // tensor-core main GEMM (mma.sync fp16)
        static int attr_set = 0;
        if (!attr_set) {
            cudaFuncSetAttribute(gemm_mma_kernel,
                                 cudaFuncAttributeMaxDynamicSharedMemorySize, SMEM_TOTAL);
            attr_set = 1;
        }
        dim3 grid(DOUT / BN, NN / BM);   // 16 x 64
        gemm_mma_kernel<<<grid, 512, SMEM_TOTAL>>>(bias, out);
    }
}

// round 7
// speedup vs baseline: 9.0747x; 1.2410x over previous
#include <cuda_runtime.h>
#include <cuda_fp16.h>
#include <cstdint>

// Problem dims (fixed)
#define NN   8192
#define DIN  4096
#define DOUT 4096
#define RK   256

// ---------------------------------------------------------------------------
// Device scratch (no runtime allocation allowed). Referenced ONLY from
// device code (passing __device__ globals as host-side kernel args is UB —
// that was the R6 failure).
// ---------------------------------------------------------------------------
__device__ __align__(256) __half g_x16[(size_t)NN * DIN];     // 64 MB
__device__ __align__(256) __half g_w16[(size_t)DOUT * DIN];   // 32 MB
__device__ __align__(256) __half g_bb16[(size_t)DOUT * RK];   // 2 MB  (b[o]*B[o][r])
__device__ __align__(256) __half g_adt16[(size_t)DIN * RK];   // 2 MB  (d[r]*A[r][i], transposed)

// ---------------------------------------------------------------------------
// PTX helpers (baseline ISA only: cp.async, ldmatrix, mma.sync)
// ---------------------------------------------------------------------------
__device__ __forceinline__ uint32_t smem_u32(const void* p) {
    uint32_t a;
    asm("{ .reg .u64 t; cvta.to.shared.u64 t, %1; cvt.u32.u64 %0, t; }" : "=r"(a) : "l"(p));
    return a;
}

#define CP_ASYNC16(dst, src) \
    asm volatile("cp.async.cg.shared.global [%0], [%1], 16;" :: "r"(dst), "l"(src) : "memory")
#define CP_ASYNC_COMMIT() asm volatile("cp.async.commit_group;" ::: "memory")
#define CP_ASYNC_WAIT(n)  asm volatile("cp.async.wait_group %0;" :: "n"(n) : "memory")

__device__ __forceinline__ void ldmatrix_x4(uint32_t* r, uint32_t addr) {
    asm volatile("ldmatrix.sync.aligned.m8n8.x4.shared.b16 {%0,%1,%2,%3}, [%4];"
                 : "=r"(r[0]), "=r"(r[1]), "=r"(r[2]), "=r"(r[3]) : "r"(addr));
}

__device__ __forceinline__ void mma16816(float* c, const uint32_t* a, const uint32_t* b) {
    asm volatile(
        "mma.sync.aligned.m16n8k16.row.col.f32.f16.f16.f32 "
        "{%0,%1,%2,%3}, {%4,%5,%6,%7}, {%8,%9}, {%0,%1,%2,%3};"
        : "+f"(c[0]), "+f"(c[1]), "+f"(c[2]), "+f"(c[3])
        : "r"(a[0]), "r"(a[1]), "r"(a[2]), "r"(a[3]), "r"(b[0]), "r"(b[1]));
}

__device__ __forceinline__ uint32_t swz(uint32_t off) {   // SW128: bits[6:4] ^= bits[9:7]
    return off ^ ((off >> 3) & 0x70);
}

// ---------------------------------------------------------------------------
// Kernel 1: convert x -> fp16
// ---------------------------------------------------------------------------
__global__ __launch_bounds__(256)
void conv_x_kernel(const float* __restrict__ x) {
    size_t i = ((size_t)blockIdx.x * blockDim.x + threadIdx.x) * 8;
    float4 a = *reinterpret_cast<const float4*>(x + i);
    float4 b = *reinterpret_cast<const float4*>(x + i + 4);
    float v[8] = {a.x, a.y, a.z, a.w, b.x, b.y, b.z, b.w};
    __align__(16) __half h[8];
    #pragma unroll
    for (int j = 0; j < 8; j++) h[j] = __float2half_rn(v[j]);
    *reinterpret_cast<uint4*>(&g_x16[i]) = *reinterpret_cast<uint4*>(h);
}

// ---------------------------------------------------------------------------
// Kernel 2a: Bb16[o][r] = fp16(b[o] * B[o][r])
// ---------------------------------------------------------------------------
__global__ __launch_bounds__(256)
void conv_b_kernel(const float* __restrict__ Bm, const float* __restrict__ bvec) {
    size_t i = ((size_t)blockIdx.x * blockDim.x + threadIdx.x) * 8;
    const int o = (int)(i / RK);
    const float s = bvec[o];
    float4 a = *reinterpret_cast<const float4*>(Bm + i);
    float4 b = *reinterpret_cast<const float4*>(Bm + i + 4);
    float v[8] = {a.x, a.y, a.z, a.w, b.x, b.y, b.z, b.w};
    __align__(16) __half h[8];
    #pragma unroll
    for (int j = 0; j < 8; j++) h[j] = __float2half_rn(v[j] * s);
    *reinterpret_cast<uint4*>(&g_bb16[i]) = *reinterpret_cast<uint4*>(h);
}

// ---------------------------------------------------------------------------
// Kernel 2b: AdT16[i][r] = fp16(d[r] * A[r][i])  (transpose, 32x32 smem tiles)
// ---------------------------------------------------------------------------
__global__ __launch_bounds__(256)
void conv_adt_kernel(const float* __restrict__ A, const float* __restrict__ dvec) {
    __shared__ float tile[32][33];
    const int r0 = blockIdx.y * 32;
    const int i0 = blockIdx.x * 32;
    const int tx = threadIdx.x & 31;
    const int ty = threadIdx.x >> 5;     // 0..7
    #pragma unroll
    for (int t = 0; t < 4; t++) {
        const int r = ty + t * 8;
        tile[r][tx] = A[(size_t)(r0 + r) * DIN + i0 + tx] * dvec[r0 + r];
    }
    __syncthreads();
    #pragma unroll
    for (int t = 0; t < 4; t++) {
        const int i = ty + t * 8;
        g_adt16[(size_t)(i0 + i) * RK + r0 + tx] = __float2half_rn(tile[tx][i]);
    }
}

// ---------------------------------------------------------------------------
// Templated NT-GEMM via mma.sync fp16. Operands chosen compile-time from
// device globals (never passed from host).
// CTA tile 128x256, KC=64 fp16 per chunk (128 B rows), NSTAGE=4, 512 threads.
//   FOLD=false: out[m][n] = sum_k x16[m][k]*w16[n][k] + bias[n]   (f32 out)
//   FOLD=true : w16[m][n] = fp16(W[m][n] + sum_k bb16[m][k]*adt16[n][k])
// ---------------------------------------------------------------------------
#define BM 128
#define BN 256
#define KC 64
#define A_BYTES (BM * 128)              // 16384
#define B_BYTES (BN * 128)              // 32768
#define STAGE_BYTES (A_BYTES + B_BYTES) // 49152
#define NSTAGE 4
#define SMEM_TOTAL (NSTAGE * STAGE_BYTES)  // 196608

template<bool FOLD>
__device__ __forceinline__ void load_chunk(int chunk, uint32_t st, int tid,
                                           int m0, int n0) {
    const int KSTRIDE = FOLD ? RK : DIN;
    const __half* __restrict__ Aop = FOLD ? g_bb16 : g_x16;
    const __half* __restrict__ Bop = FOLD ? g_adt16 : g_w16;

    const int koff = chunk * KC;
    const int seg = tid & 7;        // 16B segment within 128B row
    const int rb  = tid >> 3;       // 0..63
    #pragma unroll
    for (int t = 0; t < 2; t++) {   // A: 128 rows
        const int r = t * 64 + rb;
        const __half* g = Aop + (size_t)(m0 + r) * KSTRIDE + koff + seg * 8;
        uint32_t off = r * 128 + seg * 16;
        CP_ASYNC16(st + swz(off), g);
    }
    #pragma unroll
    for (int t = 0; t < 4; t++) {   // B: 256 rows
        const int r = t * 64 + rb;
        const __half* g = Bop + (size_t)(n0 + r) * KSTRIDE + koff + seg * 8;
        uint32_t off = r * 128 + seg * 16;
        CP_ASYNC16(st + A_BYTES + swz(off), g);
    }
}

template<bool FOLD>
__global__ __launch_bounds__(512, 1)
void gemm_tpl(const float* __restrict__ aux,   // bias (FOLD=0) or W (FOLD=1)
              float* __restrict__ outf) {      // main output (FOLD=0 only)
    const int NCHUNK = FOLD ? (RK / KC) : (DIN / KC);

    extern __shared__ char smem[];
    const uint32_t sb = smem_u32(smem);
    const int tid  = threadIdx.x;
    const int lane = tid & 31;
    const int wid  = tid >> 5;          // 0..15
    const int warp_m = wid & 1;         // 0..1  -> 64-row slab
    const int warp_n = wid >> 1;        // 0..7  -> 32-col slab

    const int n0 = blockIdx.x * BN;
    const int m0 = blockIdx.y * BM;

    float acc[4][4][4] = {};            // [mt][nt][4]

    const int arow = lane & 15;
    const int acol = (lane >> 4) * 8;
    const int brow = (lane & 7) + ((lane >> 4) << 3);
    const int bcol = ((lane >> 3) & 1) * 8;

    // Prologue: stages 0..2
    load_chunk<FOLD>(0, sb, tid, m0, n0);
    CP_ASYNC_COMMIT();
    load_chunk<FOLD>(1, sb + STAGE_BYTES, tid, m0, n0);
    CP_ASYNC_COMMIT();
    load_chunk<FOLD>(2, sb + 2 * STAGE_BYTES, tid, m0, n0);
    CP_ASYNC_COMMIT();

    for (int i = 0; i < NCHUNK; i++) {
        const uint32_t st = sb + (i % NSTAGE) * STAGE_BYTES;

        if (i < NCHUNK - 2)       { CP_ASYNC_WAIT(2); }
        else if (i == NCHUNK - 2) { CP_ASYNC_WAIT(1); }
        else                      { CP_ASYNC_WAIT(0); }
        __syncthreads();

        if (i + 3 < NCHUNK) {
            load_chunk<FOLD>(i + 3, sb + ((i + 3) % NSTAGE) * STAGE_BYTES,
                             tid, m0, n0);
            CP_ASYNC_COMMIT();
        }

        #pragma unroll
        for (int ks = 0; ks < 4; ks++) {
            uint32_t a[4][4];
            #pragma unroll
            for (int mt = 0; mt < 4; mt++) {
                uint32_t off = (uint32_t)(warp_m * 64 + mt * 16 + arow) * 128
                             + (ks * 16 + acol) * 2;
                ldmatrix_x4(a[mt], st + swz(off));
            }
            uint32_t b[4][2];
            #pragma unroll
            for (int bg = 0; bg < 2; bg++) {
                uint32_t r[4];
                uint32_t off = (uint32_t)(warp_n * 32 + bg * 16 + brow) * 128
                             + (ks * 16 + bcol) * 2;
                ldmatrix_x4(r, st + A_BYTES + swz(off));
                b[bg * 2 + 0][0] = r[0]; b[bg * 2 + 0][1] = r[1];
                b[bg * 2 + 1][0] = r[2]; b[bg * 2 + 1][1] = r[3];
            }
            #pragma unroll
            for (int mt = 0; mt < 4; mt++)
                #pragma unroll
                for (int nt = 0; nt < 4; nt++)
                    mma16816(acc[mt][nt], a[mt], b[nt]);
        }
        __syncthreads();
    }

    // Epilogue
    const int r0 = m0 + warp_m * 64 + (lane >> 2);
    const int c0 = n0 + warp_n * 32 + (lane & 3) * 2;
    #pragma unroll
    for (int mt = 0; mt < 4; mt++) {
        const int rm = r0 + mt * 16;
        #pragma unroll
        for (int nt = 0; nt < 4; nt++) {
            const int cb = c0 + nt * 8;
            if (FOLD) {
                const float2 w0 = *reinterpret_cast<const float2*>(&aux[(size_t)rm * DIN + cb]);
                const float2 w1 = *reinterpret_cast<const float2*>(&aux[(size_t)(rm + 8) * DIN + cb]);
                __half2 h0, h1;
                h0.x = __float2half_rn(w0.x + acc[mt][nt][0]);
                h0.y = __float2half_rn(w0.y + acc[mt][nt][1]);
                h1.x = __float2half_rn(w1.x + acc[mt][nt][2]);
                h1.y = __float2half_rn(w1.y + acc[mt][nt][3]);
                *reinterpret_cast<__half2*>(&g_w16[(size_t)rm * DIN + cb]) = h0;
                *reinterpret_cast<__half2*>(&g_w16[(size_t)(rm + 8) * DIN + cb]) = h1;
            } else {
                const float2 bb = *reinterpret_cast<const float2*>(&aux[cb]);
                float2 v0, v1;
                v0.x = acc[mt][nt][0] + bb.x;
                v0.y = acc[mt][nt][1] + bb.y;
                v1.x = acc[mt][nt][2] + bb.x;
                v1.y = acc[mt][nt][3] + bb.y;
                *reinterpret_cast<float2*>(&outf[(size_t)rm * DOUT + cb]) = v0;
                *reinterpret_cast<float2*>(&outf[(size_t)(rm + 8) * DOUT + cb]) = v1;
            }
        }
    }
}

// ---------------------------------------------------------------------------
// Harness entry. Inputs: x, W, bias, A_frozen, B_frozen, b_vec, d_vec.
// ---------------------------------------------------------------------------
extern "C" void kernel_launch(void* const* d_in, const int* in_sizes, int n_in,
                              void* d_out, int out_size) {
    const float* x    = (const float*)d_in[0];
    const float* W    = (const float*)d_in[1];
    const float* bias = (const float*)d_in[2];
    const float* A    = (const float*)d_in[3];
    const float* Bm   = (const float*)d_in[4];
    const float* bvec = (const float*)d_in[5];
    const float* dvec = (const float*)d_in[6];
    float* out = (float*)d_out;

    static int attr_set = 0;
    if (!attr_set) {
        cudaFuncSetAttribute(gemm_tpl<false>,
                             cudaFuncAttributeMaxDynamicSharedMemorySize, SMEM_TOTAL);
        cudaFuncSetAttribute(gemm_tpl<true>,
                             cudaFuncAttributeMaxDynamicSharedMemorySize, SMEM_TOTAL);
        attr_set = 1;
    }

    // fp16 conversions (all write device globals from device code)
    conv_x_kernel<<<(unsigned)((size_t)NN * DIN / 8 / 256), 256>>>(x);
    conv_b_kernel<<<(unsigned)((size_t)DOUT * RK / 8 / 256), 256>>>(Bm, bvec);
    {
        dim3 grid(DIN / 32, RK / 32);
        conv_adt_kernel<<<grid, 256>>>(A, dvec);
    }

    // Fold: w16 = fp16(W + bb16 @ adt16^T), K = RK
    {
        dim3 grid(DIN / BN, DOUT / BM);     // 16 x 32
        gemm_tpl<true><<<grid, 512, SMEM_TOTAL>>>(W, nullptr);
    }
    // Main GEMM: out = x16 @ w16^T + bias, K = DIN
    {
        dim3 grid(DOUT / BN, NN / BM);      // 16 x 64
        gemm_tpl<false><<<grid, 512, SMEM_TOTAL>>>(bias, out);
    }
}